// round 15
// baseline (speedup 1.0000x reference)
#include <cuda_runtime.h>
#include <cuda_fp16.h>

#define D 128
#define MAX_DRUG 10000
#define MAX_DIS  15000
#define MAX_E    1048576
#define KC 16            // k-chunk per smem stage (proj)
#define NB 640           // row buckets, 16 rows each (covers 10240 rows)
#define HB 512           // edge chunks (scatter blocks)
#define SLAB 4096        // per-bucket record capacity (mean 1678 @ E=1M)
#define SPLIT 4          // blocks per bucket in the edge kernel
#define EW 8             // warps per edge block
#define EPB (EW * 16)    // edges per edge-block iteration

// Projected embeddings in fp16 (fp32 math, rounded once).
__device__ __half g_Ah[MAX_DRUG * D];   // z_drug    @ W1[0:128]  + b1
__device__ __half g_Bh[MAX_DIS  * D];   // z_disease @ W1[128:256]
// Slab scatter state. g_cnt/g_done zero at module load; re-armed by the
// edge kernel's ticket protocol every launch (graph-replay safe).
__device__ int  g_cnt[NB];
__device__ int  g_done[NB];
// Record encoding: (col << 8) | r_local. col*256 is exactly the byte
// offset of the B row (256B rows), so the edge kernel needs only an AND.
__device__ int2 g_rec[NB * SLAB];

// ---------------------------------------------------------------------------
// K1: fused projection GEMMs + slab scatter.
// Blocks [0, tiles): 128x128 projection tiles (fp32 math, fp16 store).
// Blocks [tiles, tiles+HB): scatter — smem hist over a contiguous edge
// chunk, one global atomicAdd per (block,bucket) reserves a slab range,
// then bump-writes records. Scatter blocks backfill proj wave holes.
// ---------------------------------------------------------------------------
__global__ __launch_bounds__(256) void proj_scatter_kernel(
    const float* __restrict__ Zd, const float* __restrict__ Zs_,
    int n_drug, int n_dis,
    const float* __restrict__ W1, const float* __restrict__ b1,
    __half* __restrict__ A, __half* __restrict__ B,
    const int* __restrict__ row, const int* __restrict__ col,
    int E, int tiles, int do_scatter)
{
    __shared__ __align__(16) char smbuf[2 * KC * 128 * 4];   // 16 KB
    const int t = threadIdx.x;

    if ((int)blockIdx.x >= tiles) {                 // ---- scatter blocks
        if (!do_scatter) return;
        int* hc = (int*)smbuf;                      // NB ints (2.5KB)
        const int hb = blockIdx.x - tiles;
        const int cs = (E + HB - 1) / HB;
        const int e0 = hb * cs;
        const int e1 = min(e0 + cs, E);

        for (int i = t; i < NB; i += 256) hc[i] = 0;
        __syncthreads();
        for (int e = e0 + t; e < e1; e += 256)
            atomicAdd(&hc[row[e] >> 4], 1);
        __syncthreads();
        // Reserve slab ranges: hc[i] becomes this block's global base.
        for (int i = t; i < NB; i += 256) {
            const int v = hc[i];
            if (v) hc[i] = atomicAdd(&g_cnt[i], v);
        }
        __syncthreads();

        // Bump-write records (4-edge ILP). rec.x = (col<<8) | r_local.
        int e = e0 + t;
        for (; e + 768 < e1; e += 1024) {
            const int r0v = row[e];
            const int r1v = row[e + 256];
            const int r2v = row[e + 512];
            const int r3v = row[e + 768];
            const int c0v = col[e];
            const int c1v = col[e + 256];
            const int c2v = col[e + 512];
            const int c3v = col[e + 768];
            const int p0 = atomicAdd(&hc[r0v >> 4], 1);
            const int p1 = atomicAdd(&hc[r1v >> 4], 1);
            const int p2 = atomicAdd(&hc[r2v >> 4], 1);
            const int p3 = atomicAdd(&hc[r3v >> 4], 1);
            g_rec[(r0v >> 4) * SLAB + p0] = make_int2((c0v << 8) | (r0v & 15), e);
            g_rec[(r1v >> 4) * SLAB + p1] = make_int2((c1v << 8) | (r1v & 15), e + 256);
            g_rec[(r2v >> 4) * SLAB + p2] = make_int2((c2v << 8) | (r2v & 15), e + 512);
            g_rec[(r3v >> 4) * SLAB + p3] = make_int2((c3v << 8) | (r3v & 15), e + 768);
        }
        for (; e < e1; e += 256) {
            const int r = row[e];
            const int c = col[e];
            const int p = atomicAdd(&hc[r >> 4], 1);
            g_rec[(r >> 4) * SLAB + p] = make_int2((c << 8) | (r & 15), e);
        }
        return;
    }

    // ---- projection blocks (128 rows x 128 cols, 8x8 register tile)
    const int tiles_drug = (n_drug + 127) / 128;
    const float* Z;
    __half* out;
    int N, koff, addb;
    int tile = blockIdx.x;
    if (tile < tiles_drug) { Z = Zd;  out = A; N = n_drug; koff = 0;   addb = 1; }
    else { tile -= tiles_drug; Z = Zs_; out = B; N = n_dis; koff = 128; addb = 0; }
    const int r0 = tile * 128;

    float (*Zt)[128] = (float(*)[128])smbuf;                    // [KC][128]
    float (*Wt)[128] = (float(*)[128])(smbuf + KC * 128 * 4);   // [KC][128]

    const int tx = t & 15;          // col group: cols tx*8 .. tx*8+7
    const int ty = t >> 4;          // row group: rows ty*8 .. ty*8+7

    float acc[8][8];
#pragma unroll
    for (int i = 0; i < 8; i++)
#pragma unroll
        for (int j = 0; j < 8; j++) acc[i][j] = 0.f;

    for (int kc = 0; kc < D; kc += KC) {
        __syncthreads();
        // Z tile: 128 rows x 16 k = 512 float4, transposed STS.
#pragma unroll
        for (int i = t; i < 512; i += 256) {
            const int rr = i & 127;
            const int k4 = i >> 7;
            float4 v = make_float4(0.f, 0.f, 0.f, 0.f);
            if (r0 + rr < N)
                v = *reinterpret_cast<const float4*>(
                        Z + (size_t)(r0 + rr) * D + kc + k4 * 4);
            Zt[k4 * 4 + 0][rr] = v.x;
            Zt[k4 * 4 + 1][rr] = v.y;
            Zt[k4 * 4 + 2][rr] = v.z;
            Zt[k4 * 4 + 3][rr] = v.w;
        }
        // W1 chunk: 16 k-rows x 128 cols, coalesced float4.
#pragma unroll
        for (int i = t; i < 512; i += 256) {
            const int kk = i >> 5;
            const int c4 = i & 31;
            *reinterpret_cast<float4*>(&Wt[kk][c4 * 4]) =
                *reinterpret_cast<const float4*>(
                    W1 + (size_t)(koff + kc + kk) * D + c4 * 4);
        }
        __syncthreads();

#pragma unroll
        for (int kk = 0; kk < KC; kk++) {
            float af[8], bf[8];
            *reinterpret_cast<float4*>(af)     = *reinterpret_cast<float4*>(&Zt[kk][ty * 8]);
            *reinterpret_cast<float4*>(af + 4) = *reinterpret_cast<float4*>(&Zt[kk][ty * 8 + 4]);
            *reinterpret_cast<float4*>(bf)     = *reinterpret_cast<float4*>(&Wt[kk][tx * 8]);
            *reinterpret_cast<float4*>(bf + 4) = *reinterpret_cast<float4*>(&Wt[kk][tx * 8 + 4]);
#pragma unroll
            for (int i = 0; i < 8; i++)
#pragma unroll
                for (int j = 0; j < 8; j++)
                    acc[i][j] = fmaf(af[i], bf[j], acc[i][j]);
        }
    }

    float bias[8];
#pragma unroll
    for (int j = 0; j < 8; j++) bias[j] = addb ? b1[tx * 8 + j] : 0.f;

#pragma unroll
    for (int i = 0; i < 8; i++) {
        const int r = r0 + ty * 8 + i;
        if (r < N) {
            __half2 h[4];
#pragma unroll
            for (int j = 0; j < 4; j++)
                h[j] = __floats2half2_rn(acc[i][2 * j]     + bias[2 * j],
                                         acc[i][2 * j + 1] + bias[2 * j + 1]);
            *reinterpret_cast<uint4*>(out + (size_t)r * D + tx * 8) =
                *reinterpret_cast<uint4*>(h);
        }
    }
}

// ---------------------------------------------------------------------------
// K2: bucketed edge compute (fold reduction). 256 threads, SPLIT=4 per
// bucket, >=5 blocks/SM. Records pre-scaled: B byte addr = rx & ~255,
// A smem index = (rx & 15)*16 + j. Compute in two 4-pair groups to
// shorten bv live ranges. Ticket protocol re-arms g_cnt.
// ---------------------------------------------------------------------------
__global__ __launch_bounds__(256, 5) void edge_sorted_kernel(
    const float* __restrict__ W2, const float* __restrict__ b2,
    float* __restrict__ out, int n_drug)
{
    __shared__ uint4 As4[16 * 16];

    const int t    = threadIdx.x;
    const int b    = blockIdx.x / SPLIT;
    const int part = blockIdx.x % SPLIT;

    {   // stage this bucket's 16 A rows (4KB), one chunk per thread
        const uint4* A16 = reinterpret_cast<const uint4*>(g_Ah);
        const int r = b * 16 + (t >> 4);
        As4[t] = (r < n_drug) ? A16[r * 16 + (t & 15)]
                              : make_uint4(0u, 0u, 0u, 0u);
    }
    __syncthreads();

    const int s0  = b * SLAB;
    const int len = min(g_cnt[b], SLAB);
    const int q0  = s0 + (len * part) / SPLIT;
    const int q1  = s0 + (len * (part + 1)) / SPLIT;

    if (q0 < q1) {
        const int lane = t & 31;
        const int wid  = t >> 5;
        const int l4   = lane & 15;      // lane within half-warp
        const int j    = l4;             // 16B chunk within a 256B row
        const int hi   = lane >> 4;      // half-warp id

        const bool loader  = (lane & 8) == 0;
        const int  loadoff = (lane & 7) + hi * 8;

        // Fold mapping: lane ends holding value index vidx = b3*4+b2*2+b1.
        const int vidx   = ((l4 >> 3) & 1) * 4 + ((l4 >> 2) & 1) * 2 + ((l4 >> 1) & 1);
        const int eidsrc = vidx + hi * 16;
        const bool writer = (l4 & 1) == 0;

        const float4 wa = reinterpret_cast<const float4*>(W2)[j * 2];
        const float4 wb = reinterpret_cast<const float4*>(W2)[j * 2 + 1];
        const __half2 w0  = __floats2half2_rn(wa.x, wa.y);
        const __half2 w1  = __floats2half2_rn(wa.z, wa.w);
        const __half2 w2h = __floats2half2_rn(wb.x, wb.y);
        const __half2 w3  = __floats2half2_rn(wb.z, wb.w);
        const float bias = b2[0];
        const __half2 zero = __float2half2_rn(0.f);
        const char* __restrict__ Bbytes = reinterpret_cast<const char*>(g_Bh) + j * 16;
        const unsigned full = 0xffffffffu;

        auto pair_dot = [&](const uint4& a, const uint4& bv) -> float {
            __half2 h0 = __hmax2(__hadd2(*reinterpret_cast<const __half2*>(&a.x),
                                         *reinterpret_cast<const __half2*>(&bv.x)), zero);
            __half2 h1 = __hmax2(__hadd2(*reinterpret_cast<const __half2*>(&a.y),
                                         *reinterpret_cast<const __half2*>(&bv.y)), zero);
            __half2 h2 = __hmax2(__hadd2(*reinterpret_cast<const __half2*>(&a.z),
                                         *reinterpret_cast<const __half2*>(&bv.z)), zero);
            __half2 h3 = __hmax2(__hadd2(*reinterpret_cast<const __half2*>(&a.w),
                                         *reinterpret_cast<const __half2*>(&bv.w)), zero);
            __half2 acc0 = __hfma2(h1, w1, __hmul2(h0, w0));
            __half2 acc1 = __hfma2(h3, w3, __hmul2(h2, w2h));
            float2 f0 = __half22float2(acc0);
            float2 f1 = __half22float2(acc1);
            return (f0.x + f0.y) + (f1.x + f1.y);
        };

        const bool b3  = (l4 & 8) != 0;
        const bool b2f = (l4 & 4) != 0;
        const bool b1f = (l4 & 2) != 0;

        int base = q0 + wid * 16;
        int2 rec = make_int2(0, 0);
        if (base < q1 && loader)
            rec = g_rec[min(base + loadoff, q1 - 1)];

        for (; base < q1; base += EPB) {
            const int nbase = base + EPB;
            int2 recn = make_int2(0, 0);
            if (nbase < q1 && loader)
                recn = g_rec[min(nbase + loadoff, q1 - 1)];

            const int n = min(16, q1 - base);

            int rx[8];
#pragma unroll
            for (int p = 0; p < 8; p++)
                rx[p] = __shfl_sync(full, rec.x, p + hi * 16);

            float s[8];
            // Group 0: pairs 0-3 — load, then dot while group 1 loads.
            uint4 bv0[4];
#pragma unroll
            for (int p = 0; p < 4; p++)
                bv0[p] = *reinterpret_cast<const uint4*>(
                    Bbytes + ((unsigned)rx[p] & 0xFFFFFF00u));
            uint4 bv1[4];
#pragma unroll
            for (int p = 0; p < 4; p++)
                bv1[p] = *reinterpret_cast<const uint4*>(
                    Bbytes + ((unsigned)rx[p + 4] & 0xFFFFFF00u));
#pragma unroll
            for (int p = 0; p < 4; p++)
                s[p] = pair_dot(As4[((rx[p] & 15) << 4) + j], bv0[p]);
#pragma unroll
            for (int p = 0; p < 4; p++)
                s[p + 4] = pair_dot(As4[((rx[p + 4] & 15) << 4) + j], bv1[p]);

            // Fold reduction: 8 SHFL total.
            float tq[4];
#pragma unroll
            for (int q = 0; q < 4; q++) {
                float keep  = b3 ? s[q + 4] : s[q];
                float other = b3 ? s[q] : s[q + 4];
                tq[q] = keep + __shfl_xor_sync(full, other, 8);
            }
            float ur[2];
#pragma unroll
            for (int r = 0; r < 2; r++) {
                float keep  = b2f ? tq[r + 2] : tq[r];
                float other = b2f ? tq[r] : tq[r + 2];
                ur[r] = keep + __shfl_xor_sync(full, other, 4);
            }
            float v;
            {
                float keep  = b1f ? ur[1] : ur[0];
                float other = b1f ? ur[0] : ur[1];
                v = keep + __shfl_xor_sync(full, other, 2);
            }
            v += __shfl_xor_sync(full, v, 1);

            const int eid = __shfl_sync(full, rec.y, eidsrc);
            if (writer && (vidx + hi * 8) < n)
                out[eid] = v + bias;

            rec = recn;
        }
    }

    // Ticket protocol: all threads of this block have read g_cnt[b]
    // (barrier below), so the last finishing block may safely zero it
    // for the next graph replay.
    __syncthreads();
    if (t == 0) {
        const int old = atomicAdd(&g_done[b], 1);
        if (old == SPLIT - 1) {
            g_cnt[b] = 0;
            g_done[b] = 0;
        }
    }
}

// ---------------------------------------------------------------------------
// Fallback flat edge kernel (round-4 design, known-good) for odd shapes.
// ---------------------------------------------------------------------------
__global__ __launch_bounds__(256) void edge_kernel_flat(
    const int* __restrict__ row, const int* __restrict__ col,
    const float* __restrict__ W2, const float* __restrict__ b2,
    float* __restrict__ out, int E)
{
    const int lane = threadIdx.x & 31;
    const int warp = blockIdx.x * 8 + (threadIdx.x >> 5);
    const int e0 = warp * 4;
    if (e0 >= E) return;

    const float4 w2 = reinterpret_cast<const float4*>(W2)[lane];
    const float bias = b2[0];
    const int last = E - 1;

    const int r0i = row[e0];
    const int c0i = col[e0];
    const int r1i = row[min(e0 + 1, last)];
    const int c1i = col[min(e0 + 1, last)];
    const int r2i = row[min(e0 + 2, last)];
    const int c2i = col[min(e0 + 2, last)];
    const int r3i = row[min(e0 + 3, last)];
    const int c3i = col[min(e0 + 3, last)];

    const uint2* __restrict__ Ah = reinterpret_cast<const uint2*>(g_Ah);
    const uint2* __restrict__ Bh = reinterpret_cast<const uint2*>(g_Bh);
    const uint2 a0 = Ah[(size_t)r0i * 32 + lane];
    const uint2 b0 = Bh[(size_t)c0i * 32 + lane];
    const uint2 a1 = Ah[(size_t)r1i * 32 + lane];
    const uint2 b1v = Bh[(size_t)c1i * 32 + lane];
    const uint2 a2 = Ah[(size_t)r2i * 32 + lane];
    const uint2 b2v = Bh[(size_t)c2i * 32 + lane];
    const uint2 a3 = Ah[(size_t)r3i * 32 + lane];
    const uint2 b3v = Bh[(size_t)c3i * 32 + lane];

    const __half2 zero = __float2half2_rn(0.f);
    auto edge_dot = [&](uint2 a, uint2 b) -> float {
        __half2 al = *reinterpret_cast<__half2*>(&a.x);
        __half2 ah = *reinterpret_cast<__half2*>(&a.y);
        __half2 bl = *reinterpret_cast<__half2*>(&b.x);
        __half2 bh = *reinterpret_cast<__half2*>(&b.y);
        __half2 h0 = __hmax2(__hadd2(al, bl), zero);
        __half2 h1 = __hmax2(__hadd2(ah, bh), zero);
        float2 f0 = __half22float2(h0);
        float2 f1 = __half22float2(h1);
        return f0.x * w2.x + f0.y * w2.y + f1.x * w2.z + f1.y * w2.w;
    };

    float s0 = edge_dot(a0, b0);
    float s1 = edge_dot(a1, b1v);
    float s2 = edge_dot(a2, b2v);
    float s3 = edge_dot(a3, b3v);

    const unsigned full = 0xffffffffu;
    const bool hi = (lane & 16) != 0;
    float va = hi ? s1 : s0;
    float oa = hi ? s0 : s1;
    va += __shfl_xor_sync(full, oa, 16);
    float vb = hi ? s3 : s2;
    float ob = hi ? s2 : s3;
    vb += __shfl_xor_sync(full, ob, 16);
#pragma unroll
    for (int off = 8; off > 0; off >>= 1) {
        va += __shfl_xor_sync(full, va, off);
        vb += __shfl_xor_sync(full, vb, off);
    }
    if (lane == 0) {
        out[e0] = va + bias;
        if (e0 + 2 < E) out[e0 + 2] = vb + bias;
    } else if (lane == 16) {
        if (e0 + 1 < E) out[e0 + 1] = va + bias;
        if (e0 + 3 < E) out[e0 + 3] = vb + bias;
    }
}

extern "C" void kernel_launch(void* const* d_in, const int* in_sizes, int n_in,
                              void* d_out, int out_size)
{
    const float* z_drug = (const float*)d_in[0];
    const float* z_dis  = (const float*)d_in[1];
    const int*   row    = (const int*)  d_in[2];
    const int*   col    = (const int*)  d_in[3];
    const float* W1     = (const float*)d_in[4];
    const float* b1     = (const float*)d_in[5];
    const float* W2     = (const float*)d_in[6];
    const float* b2     = (const float*)d_in[7];
    float* out = (float*)d_out;

    const int n_drug = in_sizes[0] / D;
    const int n_dis  = in_sizes[1] / D;
    const int E      = in_sizes[2];

    __half *dA = nullptr, *dB = nullptr;
    cudaGetSymbolAddress((void**)&dA, g_Ah);
    cudaGetSymbolAddress((void**)&dB, g_Bh);

    const int tiles = (n_drug + 127) / 128 + (n_dis + 127) / 128;
    const bool bucketed = (E <= MAX_E) && (n_drug <= NB * 16)
                       && (n_dis < (1 << 23));

    if (bucketed) {
        proj_scatter_kernel<<<tiles + HB, 256>>>(
            z_drug, z_dis, n_drug, n_dis, W1, b1, dA, dB,
            row, col, E, tiles, 1);
        edge_sorted_kernel<<<NB * SPLIT, 256>>>(W2, b2, out, n_drug);
    } else {
        proj_scatter_kernel<<<tiles, 256>>>(
            z_drug, z_dis, n_drug, n_dis, W1, b1, dA, dB,
            row, col, E, tiles, 0);
        const int warps  = (E + 3) / 4;
        const int blocks = (warps + 7) / 8;
        edge_kernel_flat<<<blocks, 256>>>(row, col, W2, b2, out, E);
    }
}

// round 17
// speedup vs baseline: 1.1652x; 1.1652x over previous
#include <cuda_runtime.h>
#include <cuda_fp16.h>
#include <mma.h>
#include <cstdint>

using namespace nvcuda;

#define D 128
#define MAX_DRUG 10000
#define MAX_DIS  15000
#define MAX_E    1048576
#define NB 640           // row buckets, 16 rows each (covers 10240 rows)
#define HB 512           // edge chunks (scatter blocks)
#define SLAB 4096        // per-bucket record capacity (mean 1678 @ E=1M)
#define SPLIT 4          // blocks per bucket in the edge kernel
#define EW 8             // warps per edge block
#define EPB (EW * 16)    // edges per edge-block iteration
#define LDH 136          // smem leading dim (halves) for fp16 tiles
#define PROJ_DSMEM (2 * 128 * LDH * 2)   // A + B fp16 tiles = 69632 B

// Projected embeddings in fp16 (HMMA fp16 inputs, fp32 accum, rounded once).
__device__ __half g_Ah[MAX_DRUG * D];   // z_drug    @ W1[0:128]  + b1
__device__ __half g_Bh[MAX_DIS  * D];   // z_disease @ W1[128:256]
// Slab scatter state. g_cnt/g_done zero at module load; re-armed by the
// edge kernel's ticket protocol every launch (graph-replay safe).
__device__ int  g_cnt[NB];
__device__ int  g_done[NB];
// Record encoding: (col << 8) | r_local (col*256 = B-row byte offset).
__device__ int2 g_rec[NB * SLAB];

__device__ __forceinline__ uint32_t h2u(__half2 h) {
    return *reinterpret_cast<uint32_t*>(&h);
}

// ---------------------------------------------------------------------------
// K1: wmma (HMMA) projection GEMMs + fused slab scatter.
// Proj block: 128x128 output tile. A = fp16(Z tile) row-major [128,K=128];
// B = fp16(W1 half) row-major [K=128,N=128]. 8 warps x 8 fp32 acc frags.
// ---------------------------------------------------------------------------
__global__ __launch_bounds__(256) void proj_scatter_kernel(
    const float* __restrict__ Zd, const float* __restrict__ Zs_,
    int n_drug, int n_dis,
    const float* __restrict__ W1, const float* __restrict__ b1,
    __half* __restrict__ A, __half* __restrict__ B,
    const int* __restrict__ row, const int* __restrict__ col,
    int E, int tiles, int do_scatter)
{
    extern __shared__ __align__(16) char dyn[];
    const int t = threadIdx.x;

    if ((int)blockIdx.x >= tiles) {                 // ---- scatter blocks
        if (!do_scatter) return;
        int* hc = (int*)dyn;                        // NB ints
        const int hb = blockIdx.x - tiles;
        const int cs = (E + HB - 1) / HB;
        const int e0 = hb * cs;
        const int e1 = min(e0 + cs, E);

        for (int i = t; i < NB; i += 256) hc[i] = 0;
        __syncthreads();
        for (int e = e0 + t; e < e1; e += 256)
            atomicAdd(&hc[row[e] >> 4], 1);
        __syncthreads();
        for (int i = t; i < NB; i += 256) {
            const int v = hc[i];
            if (v) hc[i] = atomicAdd(&g_cnt[i], v);
        }
        __syncthreads();

        int e = e0 + t;
        for (; e + 768 < e1; e += 1024) {
            const int r0v = row[e];
            const int r1v = row[e + 256];
            const int r2v = row[e + 512];
            const int r3v = row[e + 768];
            const int c0v = col[e];
            const int c1v = col[e + 256];
            const int c2v = col[e + 512];
            const int c3v = col[e + 768];
            const int p0 = atomicAdd(&hc[r0v >> 4], 1);
            const int p1 = atomicAdd(&hc[r1v >> 4], 1);
            const int p2 = atomicAdd(&hc[r2v >> 4], 1);
            const int p3 = atomicAdd(&hc[r3v >> 4], 1);
            g_rec[(r0v >> 4) * SLAB + p0] = make_int2((c0v << 8) | (r0v & 15), e);
            g_rec[(r1v >> 4) * SLAB + p1] = make_int2((c1v << 8) | (r1v & 15), e + 256);
            g_rec[(r2v >> 4) * SLAB + p2] = make_int2((c2v << 8) | (r2v & 15), e + 512);
            g_rec[(r3v >> 4) * SLAB + p3] = make_int2((c3v << 8) | (r3v & 15), e + 768);
        }
        for (; e < e1; e += 256) {
            const int r = row[e];
            const int c = col[e];
            const int p = atomicAdd(&hc[r >> 4], 1);
            g_rec[(r >> 4) * SLAB + p] = make_int2((c << 8) | (r & 15), e);
        }
        return;
    }

    // ---- projection blocks (wmma)
    __shared__ float bias_sm[128];

    const int tiles_drug = (n_drug + 127) / 128;
    const float* Z;
    __half* out;
    int N, koff, addb;
    int tile = blockIdx.x;
    if (tile < tiles_drug) { Z = Zd;  out = A; N = n_drug; koff = 0;   addb = 1; }
    else { tile -= tiles_drug; Z = Zs_; out = B; N = n_dis; koff = 128; addb = 0; }
    const int r0 = tile * 128;

    __half* a_sm = reinterpret_cast<__half*>(dyn);                 // [128][LDH]
    __half* b_sm = a_sm + 128 * LDH;                               // [128][LDH]

    if (t < 128) bias_sm[t] = addb ? b1[t] : 0.f;

    // Stage A: fp16(Z tile) row-major. 16 coalesced float4 loads/thread.
    for (int i = t; i < 4096; i += 256) {
        const int r  = i >> 5;
        const int c4 = i & 31;
        float4 v = make_float4(0.f, 0.f, 0.f, 0.f);
        if (r0 + r < N)
            v = *reinterpret_cast<const float4*>(Z + (size_t)(r0 + r) * D + c4 * 4);
        uint2 st;
        st.x = h2u(__floats2half2_rn(v.x, v.y));
        st.y = h2u(__floats2half2_rn(v.z, v.w));
        *reinterpret_cast<uint2*>(a_sm + r * LDH + c4 * 4) = st;
    }
    // Stage B: fp16(W1 half) row-major [K][N].
    for (int i = t; i < 4096; i += 256) {
        const int k  = i >> 5;
        const int c4 = i & 31;
        const float4 v = *reinterpret_cast<const float4*>(
            W1 + (size_t)(koff + k) * D + c4 * 4);
        uint2 st;
        st.x = h2u(__floats2half2_rn(v.x, v.y));
        st.y = h2u(__floats2half2_rn(v.z, v.w));
        *reinterpret_cast<uint2*>(b_sm + k * LDH + c4 * 4) = st;
    }
    __syncthreads();

    // Compute: warp w owns rows w*16..w*16+15, all 128 cols.
    const int w    = t >> 5;
    const int lane = t & 31;

    wmma::fragment<wmma::accumulator, 16, 16, 16, float> acc[8];
#pragma unroll
    for (int n = 0; n < 8; n++) wmma::fill_fragment(acc[n], 0.f);

#pragma unroll
    for (int k = 0; k < 8; k++) {
        wmma::fragment<wmma::matrix_a, 16, 16, 16, __half, wmma::row_major> af;
        wmma::load_matrix_sync(af, a_sm + (w * 16) * LDH + k * 16, LDH);
#pragma unroll
        for (int n = 0; n < 8; n++) {
            wmma::fragment<wmma::matrix_b, 16, 16, 16, __half, wmma::row_major> bf;
            wmma::load_matrix_sync(bf, b_sm + (k * 16) * LDH + n * 16, LDH);
            wmma::mma_sync(acc[n], af, bf, acc[n]);
        }
    }
    __syncthreads();   // done reading fp16 tiles; reuse dyn as fp32 stage

    // Epilogue: park fragments in warp-private fp32 rows, then bias+round.
    float* f_sm = reinterpret_cast<float*>(dyn);   // [128][128]
#pragma unroll
    for (int n = 0; n < 8; n++)
        wmma::store_matrix_sync(f_sm + (w * 16) * 128 + n * 16, acc[n],
                                128, wmma::mem_row_major);
    __syncwarp();

    {   // lane -> (row = w*16 + lane>>1, cols (lane&1)*64 .. +63)
        const int rloc = w * 16 + (lane >> 1);
        const int gr   = r0 + rloc;
        const int c0   = (lane & 1) * 64;
        if (gr < N) {
            const float* src = f_sm + rloc * 128 + c0;
            uint4* op = reinterpret_cast<uint4*>(out + (size_t)gr * D + c0);
#pragma unroll
            for (int q = 0; q < 8; q++) {   // 8 x uint4 = 64 halves
                uint4 st;
                const int b8 = q * 8;
                st.x = h2u(__floats2half2_rn(src[b8 + 0] + bias_sm[c0 + b8 + 0],
                                             src[b8 + 1] + bias_sm[c0 + b8 + 1]));
                st.y = h2u(__floats2half2_rn(src[b8 + 2] + bias_sm[c0 + b8 + 2],
                                             src[b8 + 3] + bias_sm[c0 + b8 + 3]));
                st.z = h2u(__floats2half2_rn(src[b8 + 4] + bias_sm[c0 + b8 + 4],
                                             src[b8 + 5] + bias_sm[c0 + b8 + 5]));
                st.w = h2u(__floats2half2_rn(src[b8 + 6] + bias_sm[c0 + b8 + 6],
                                             src[b8 + 7] + bias_sm[c0 + b8 + 7]));
                op[q] = st;
            }
        }
    }
}

// ---------------------------------------------------------------------------
// K2: bucketed edge compute (fold reduction) — unchanged from round 15.
// ---------------------------------------------------------------------------
__global__ __launch_bounds__(256, 5) void edge_sorted_kernel(
    const float* __restrict__ W2, const float* __restrict__ b2,
    float* __restrict__ out, int n_drug)
{
    __shared__ uint4 As4[16 * 16];

    const int t    = threadIdx.x;
    const int b    = blockIdx.x / SPLIT;
    const int part = blockIdx.x % SPLIT;

    {   // stage this bucket's 16 A rows (4KB), one chunk per thread
        const uint4* A16 = reinterpret_cast<const uint4*>(g_Ah);
        const int r = b * 16 + (t >> 4);
        As4[t] = (r < n_drug) ? A16[r * 16 + (t & 15)]
                              : make_uint4(0u, 0u, 0u, 0u);
    }
    __syncthreads();

    const int s0  = b * SLAB;
    const int len = min(g_cnt[b], SLAB);
    const int q0  = s0 + (len * part) / SPLIT;
    const int q1  = s0 + (len * (part + 1)) / SPLIT;

    if (q0 < q1) {
        const int lane = t & 31;
        const int wid  = t >> 5;
        const int l4   = lane & 15;
        const int j    = l4;
        const int hi   = lane >> 4;

        const bool loader  = (lane & 8) == 0;
        const int  loadoff = (lane & 7) + hi * 8;

        const int vidx   = ((l4 >> 3) & 1) * 4 + ((l4 >> 2) & 1) * 2 + ((l4 >> 1) & 1);
        const int eidsrc = vidx + hi * 16;
        const bool writer = (l4 & 1) == 0;

        const float4 wa = reinterpret_cast<const float4*>(W2)[j * 2];
        const float4 wb = reinterpret_cast<const float4*>(W2)[j * 2 + 1];
        const __half2 w0  = __floats2half2_rn(wa.x, wa.y);
        const __half2 w1  = __floats2half2_rn(wa.z, wa.w);
        const __half2 w2h = __floats2half2_rn(wb.x, wb.y);
        const __half2 w3  = __floats2half2_rn(wb.z, wb.w);
        const float bias = b2[0];
        const __half2 zero = __float2half2_rn(0.f);
        const char* __restrict__ Bbytes = reinterpret_cast<const char*>(g_Bh) + j * 16;
        const unsigned full = 0xffffffffu;

        auto pair_dot = [&](const uint4& a, const uint4& bv) -> float {
            __half2 h0 = __hmax2(__hadd2(*reinterpret_cast<const __half2*>(&a.x),
                                         *reinterpret_cast<const __half2*>(&bv.x)), zero);
            __half2 h1 = __hmax2(__hadd2(*reinterpret_cast<const __half2*>(&a.y),
                                         *reinterpret_cast<const __half2*>(&bv.y)), zero);
            __half2 h2 = __hmax2(__hadd2(*reinterpret_cast<const __half2*>(&a.z),
                                         *reinterpret_cast<const __half2*>(&bv.z)), zero);
            __half2 h3 = __hmax2(__hadd2(*reinterpret_cast<const __half2*>(&a.w),
                                         *reinterpret_cast<const __half2*>(&bv.w)), zero);
            __half2 acc0 = __hfma2(h1, w1, __hmul2(h0, w0));
            __half2 acc1 = __hfma2(h3, w3, __hmul2(h2, w2h));
            float2 f0 = __half22float2(acc0);
            float2 f1 = __half22float2(acc1);
            return (f0.x + f0.y) + (f1.x + f1.y);
        };

        const bool b3  = (l4 & 8) != 0;
        const bool b2f = (l4 & 4) != 0;
        const bool b1f = (l4 & 2) != 0;

        int base = q0 + wid * 16;
        int2 rec = make_int2(0, 0);
        if (base < q1 && loader)
            rec = g_rec[min(base + loadoff, q1 - 1)];

        for (; base < q1; base += EPB) {
            const int nbase = base + EPB;
            int2 recn = make_int2(0, 0);
            if (nbase < q1 && loader)
                recn = g_rec[min(nbase + loadoff, q1 - 1)];

            const int n = min(16, q1 - base);

            int rx[8];
#pragma unroll
            for (int p = 0; p < 8; p++)
                rx[p] = __shfl_sync(full, rec.x, p + hi * 16);

            float s[8];
            uint4 bv0[4];
#pragma unroll
            for (int p = 0; p < 4; p++)
                bv0[p] = *reinterpret_cast<const uint4*>(
                    Bbytes + ((unsigned)rx[p] & 0xFFFFFF00u));
            uint4 bv1[4];
#pragma unroll
            for (int p = 0; p < 4; p++)
                bv1[p] = *reinterpret_cast<const uint4*>(
                    Bbytes + ((unsigned)rx[p + 4] & 0xFFFFFF00u));
#pragma unroll
            for (int p = 0; p < 4; p++)
                s[p] = pair_dot(As4[((rx[p] & 15) << 4) + j], bv0[p]);
#pragma unroll
            for (int p = 0; p < 4; p++)
                s[p + 4] = pair_dot(As4[((rx[p + 4] & 15) << 4) + j], bv1[p]);

            float tq[4];
#pragma unroll
            for (int q = 0; q < 4; q++) {
                float keep  = b3 ? s[q + 4] : s[q];
                float other = b3 ? s[q] : s[q + 4];
                tq[q] = keep + __shfl_xor_sync(full, other, 8);
            }
            float ur[2];
#pragma unroll
            for (int r = 0; r < 2; r++) {
                float keep  = b2f ? tq[r + 2] : tq[r];
                float other = b2f ? tq[r] : tq[r + 2];
                ur[r] = keep + __shfl_xor_sync(full, other, 4);
            }
            float v;
            {
                float keep  = b1f ? ur[1] : ur[0];
                float other = b1f ? ur[0] : ur[1];
                v = keep + __shfl_xor_sync(full, other, 2);
            }
            v += __shfl_xor_sync(full, v, 1);

            const int eid = __shfl_sync(full, rec.y, eidsrc);
            if (writer && (vidx + hi * 8) < n)
                out[eid] = v + bias;

            rec = recn;
        }
    }

    __syncthreads();
    if (t == 0) {
        const int old = atomicAdd(&g_done[b], 1);
        if (old == SPLIT - 1) {
            g_cnt[b] = 0;
            g_done[b] = 0;
        }
    }
}

// ---------------------------------------------------------------------------
// Fallback flat edge kernel (round-4 design, known-good) for odd shapes.
// ---------------------------------------------------------------------------
__global__ __launch_bounds__(256) void edge_kernel_flat(
    const int* __restrict__ row, const int* __restrict__ col,
    const float* __restrict__ W2, const float* __restrict__ b2,
    float* __restrict__ out, int E)
{
    const int lane = threadIdx.x & 31;
    const int warp = blockIdx.x * 8 + (threadIdx.x >> 5);
    const int e0 = warp * 4;
    if (e0 >= E) return;

    const float4 w2 = reinterpret_cast<const float4*>(W2)[lane];
    const float bias = b2[0];
    const int last = E - 1;

    const int r0i = row[e0];
    const int c0i = col[e0];
    const int r1i = row[min(e0 + 1, last)];
    const int c1i = col[min(e0 + 1, last)];
    const int r2i = row[min(e0 + 2, last)];
    const int c2i = col[min(e0 + 2, last)];
    const int r3i = row[min(e0 + 3, last)];
    const int c3i = col[min(e0 + 3, last)];

    const uint2* __restrict__ Ah = reinterpret_cast<const uint2*>(g_Ah);
    const uint2* __restrict__ Bh = reinterpret_cast<const uint2*>(g_Bh);
    const uint2 a0 = Ah[(size_t)r0i * 32 + lane];
    const uint2 b0 = Bh[(size_t)c0i * 32 + lane];
    const uint2 a1 = Ah[(size_t)r1i * 32 + lane];
    const uint2 b1v = Bh[(size_t)c1i * 32 + lane];
    const uint2 a2 = Ah[(size_t)r2i * 32 + lane];
    const uint2 b2v = Bh[(size_t)c2i * 32 + lane];
    const uint2 a3 = Ah[(size_t)r3i * 32 + lane];
    const uint2 b3v = Bh[(size_t)c3i * 32 + lane];

    const __half2 zero = __float2half2_rn(0.f);
    auto edge_dot = [&](uint2 a, uint2 b) -> float {
        __half2 al = *reinterpret_cast<__half2*>(&a.x);
        __half2 ah = *reinterpret_cast<__half2*>(&a.y);
        __half2 bl = *reinterpret_cast<__half2*>(&b.x);
        __half2 bh = *reinterpret_cast<__half2*>(&b.y);
        __half2 h0 = __hmax2(__hadd2(al, bl), zero);
        __half2 h1 = __hmax2(__hadd2(ah, bh), zero);
        float2 f0 = __half22float2(h0);
        float2 f1 = __half22float2(h1);
        return f0.x * w2.x + f0.y * w2.y + f1.x * w2.z + f1.y * w2.w;
    };

    float s0 = edge_dot(a0, b0);
    float s1 = edge_dot(a1, b1v);
    float s2 = edge_dot(a2, b2v);
    float s3 = edge_dot(a3, b3v);

    const unsigned full = 0xffffffffu;
    const bool hi = (lane & 16) != 0;
    float va = hi ? s1 : s0;
    float oa = hi ? s0 : s1;
    va += __shfl_xor_sync(full, oa, 16);
    float vb = hi ? s3 : s2;
    float ob = hi ? s2 : s3;
    vb += __shfl_xor_sync(full, ob, 16);
#pragma unroll
    for (int off = 8; off > 0; off >>= 1) {
        va += __shfl_xor_sync(full, va, off);
        vb += __shfl_xor_sync(full, vb, off);
    }
    if (lane == 0) {
        out[e0] = va + bias;
        if (e0 + 2 < E) out[e0 + 2] = vb + bias;
    } else if (lane == 16) {
        if (e0 + 1 < E) out[e0 + 1] = va + bias;
        if (e0 + 3 < E) out[e0 + 3] = vb + bias;
    }
}

extern "C" void kernel_launch(void* const* d_in, const int* in_sizes, int n_in,
                              void* d_out, int out_size)
{
    const float* z_drug = (const float*)d_in[0];
    const float* z_dis  = (const float*)d_in[1];
    const int*   row    = (const int*)  d_in[2];
    const int*   col    = (const int*)  d_in[3];
    const float* W1     = (const float*)d_in[4];
    const float* b1     = (const float*)d_in[5];
    const float* W2     = (const float*)d_in[6];
    const float* b2     = (const float*)d_in[7];
    float* out = (float*)d_out;

    const int n_drug = in_sizes[0] / D;
    const int n_dis  = in_sizes[1] / D;
    const int E      = in_sizes[2];

    __half *dA = nullptr, *dB = nullptr;
    cudaGetSymbolAddress((void**)&dA, g_Ah);
    cudaGetSymbolAddress((void**)&dB, g_Bh);

    cudaFuncSetAttribute(proj_scatter_kernel,
                         cudaFuncAttributeMaxDynamicSharedMemorySize, PROJ_DSMEM);

    const int tiles = (n_drug + 127) / 128 + (n_dis + 127) / 128;
    const bool bucketed = (E <= MAX_E) && (n_drug <= NB * 16)
                       && (n_dis < (1 << 23));

    if (bucketed) {
        proj_scatter_kernel<<<tiles + HB, 256, PROJ_DSMEM>>>(
            z_drug, z_dis, n_drug, n_dis, W1, b1, dA, dB,
            row, col, E, tiles, 1);
        edge_sorted_kernel<<<NB * SPLIT, 256>>>(W2, b2, out, n_drug);
    } else {
        proj_scatter_kernel<<<tiles, 256, PROJ_DSMEM>>>(
            z_drug, z_dis, n_drug, n_dis, W1, b1, dA, dB,
            row, col, E, tiles, 0);
        const int warps  = (E + 3) / 4;
        const int blocks = (warps + 7) / 8;
        edge_kernel_flat<<<blocks, 256>>>(row, col, W2, b2, out, E);
    }
}